// round 12
// baseline (speedup 1.0000x reference)
#include <cuda_runtime.h>
#include <math.h>

#define N_NODES 50000
#define E_MAX   800000
#define D_H 64
#define KC 16   // K-chunk for tf32 GEMM

// Scratch (device globals -- no allocation allowed)
__device__ float g_p[N_NODES * D_H];      // x @ Wl
__device__ float g_base[N_NODES * D_H];   // x @ Wr + bl
__device__ float g_h[N_NODES * D_H];      // elu(...) -> next layer input
__device__ int   g_cnt[N_NODES];
__device__ float g_inv[N_NODES];
__device__ int   g_row[N_NODES + 1];      // CSR row offsets (by dst)
__device__ int   g_cursor[N_NODES];
__device__ int   g_csr[E_MAX];            // src indices grouped by dst
__device__ int   g_src[E_MAX];
__device__ int   g_dst[E_MAX];
__device__ float4 g_a[N_NODES];           // h @ Wp_top + bp
__device__ float4 g_b[N_NODES];           // h @ Wp_bot

__device__ __forceinline__ unsigned f2tf32(float x) {
    unsigned r;
    asm("cvt.rna.tf32.f32 %0, %1;" : "=r"(r) : "f"(x));
    return r;
}

__device__ __forceinline__ void mma_tf32(float c[4],
        unsigned a0, unsigned a1, unsigned a2, unsigned a3,
        unsigned b0, unsigned b1) {
    asm volatile(
        "mma.sync.aligned.m16n8k8.row.col.f32.tf32.tf32.f32 "
        "{%0,%1,%2,%3}, {%4,%5,%6,%7}, {%8,%9}, {%0,%1,%2,%3};"
        : "+f"(c[0]), "+f"(c[1]), "+f"(c[2]), "+f"(c[3])
        : "r"(a0), "r"(a1), "r"(a2), "r"(a3), "r"(b0), "r"(b1));
}

__global__ void zero_cnt_kernel() {
    int i = blockIdx.x * blockDim.x + threadIdx.x;
    if (i < N_NODES) g_cnt[i] = 0;
}

// decode src/dst (+ count degrees) in one pass. int64-vs-int32 detection is
// done per block from the first 128 words (all L2-broadcast): for int64
// indices < 2^31 every odd word is 0; for 64 random int32 indices it isn't.
__global__ void convert_count_kernel(const int* __restrict__ w, int E) {
    __shared__ int is64_s;
    if (threadIdx.x == 0) {
        int z = 1;
        for (int i = 1; i < 129; i += 2)
            if (w[i] != 0) { z = 0; break; }
        is64_s = z;
    }
    __syncthreads();
    int is64 = is64_s;
    int e = blockIdx.x * blockDim.x + threadIdx.x;
    if (e >= E) return;
    int s, d;
    if (is64) { s = w[2 * e]; d = w[2 * (E + e)]; }
    else      { s = w[e];     d = w[E + e]; }
    g_src[e] = s;
    g_dst[e] = d;
    atomicAdd(&g_cnt[d], 1);
}

// Single block, 1024 threads: exclusive scan of g_cnt -> g_row, g_cursor, g_inv
__global__ void scan_kernel() {
    __shared__ int sums[1024];
    int t = threadIdx.x;
    const int CH = (N_NODES + 1023) / 1024;
    int begin = t * CH;
    int end = begin + CH; if (end > N_NODES) end = N_NODES;
    int s = 0;
    for (int i = begin; i < end; i++) s += g_cnt[i];
    sums[t] = s;
    __syncthreads();
    for (int off = 1; off < 1024; off <<= 1) {
        int v = (t >= off) ? sums[t - off] : 0;
        __syncthreads();
        sums[t] += v;
        __syncthreads();
    }
    int run = (t == 0) ? 0 : sums[t - 1];
    for (int i = begin; i < end; i++) {
        g_row[i] = run;
        g_cursor[i] = run;
        int c = g_cnt[i];
        run += c;
        g_inv[i] = 1.0f / (float)(c > 1 ? c : 1);
    }
    if (t == 1023) g_row[N_NODES] = run;
}

__global__ void fill_kernel(int E) {
    int e = blockIdx.x * blockDim.x + threadIdx.x;
    if (e < E) {
        int pos = atomicAdd(&g_cursor[g_dst[e]], 1);
        g_csr[pos] = g_src[e];
    }
}

// Fused dual GEMM on tensor cores (tf32, 3-term split precision):
//   P = X @ Wl ; BASE = X @ Wr + bl.   (R11 version, proven)
__global__ void __launch_bounds__(256) gemm2_kernel(
        const float* __restrict__ X,
        const float* __restrict__ Wl, const float* __restrict__ Wr,
        const float* __restrict__ bl,
        float* __restrict__ P, float* __restrict__ BASE,
        int N, int K) {
    __shared__ float Xh[KC][72], Xlo[KC][72];     // [k][row], rows 0..63
    __shared__ float Wh[KC][136], Wlo[KC][136];   // [k][combined col 0..127]
    int tid  = threadIdx.x;
    int warp = tid >> 5, lane = tid & 31;
    int gid  = lane >> 2, tig = lane & 3;
    int rg   = warp >> 1;            // row group: rows rg*16..rg*16+15
    int chf  = warp & 1;             // col half:  cols chf*64..chf*64+63
    int row0 = blockIdx.x * 64;

    float acc[8][4];
#pragma unroll
    for (int j = 0; j < 8; j++)
#pragma unroll
        for (int q = 0; q < 4; q++) acc[j][q] = 0.0f;

    for (int k0 = 0; k0 < K; k0 += KC) {
        {
            int r  = tid >> 2;           // 0..63
            int kq = (tid & 3) * 4;      // 0,4,8,12
            int grow = row0 + r;
            float4 v = make_float4(0.f, 0.f, 0.f, 0.f);
            if (grow < N) v = *(const float4*)(X + (long)grow * K + k0 + kq);
            float xv[4] = {v.x, v.y, v.z, v.w};
#pragma unroll
            for (int u = 0; u < 4; u++) {
                unsigned h = f2tf32(xv[u]);
                float hf = __uint_as_float(h);
                Xh[kq + u][r]  = hf;
                Xlo[kq + u][r] = __uint_as_float(f2tf32(xv[u] - hf));
            }
        }
#pragma unroll
        for (int i = 0; i < 2; i++) {
            int f  = tid + i * 256;      // 0..511 float4 slots
            int k  = f >> 5;             // 0..15
            int c0 = (f & 31) * 4;       // 0..124
            const float* src = (c0 < 64) ? (Wl + (k0 + k) * 64 + c0)
                                         : (Wr + (k0 + k) * 64 + c0 - 64);
            float4 v = *(const float4*)src;
            float wv[4] = {v.x, v.y, v.z, v.w};
#pragma unroll
            for (int u = 0; u < 4; u++) {
                unsigned h = f2tf32(wv[u]);
                float hf = __uint_as_float(h);
                Wh[k][c0 + u]  = hf;
                Wlo[k][c0 + u] = __uint_as_float(f2tf32(wv[u] - hf));
            }
        }
        __syncthreads();

#pragma unroll
        for (int ks = 0; ks < KC; ks += 8) {
            int arow = rg * 16 + gid;
            unsigned ah[4], al[4];
            ah[0] = __float_as_uint(Xh[ks + tig][arow]);
            ah[1] = __float_as_uint(Xh[ks + tig][arow + 8]);
            ah[2] = __float_as_uint(Xh[ks + tig + 4][arow]);
            ah[3] = __float_as_uint(Xh[ks + tig + 4][arow + 8]);
            al[0] = __float_as_uint(Xlo[ks + tig][arow]);
            al[1] = __float_as_uint(Xlo[ks + tig][arow + 8]);
            al[2] = __float_as_uint(Xlo[ks + tig + 4][arow]);
            al[3] = __float_as_uint(Xlo[ks + tig + 4][arow + 8]);
#pragma unroll
            for (int j = 0; j < 8; j++) {
                int bn = chf * 64 + j * 8 + gid;
                unsigned bh0 = __float_as_uint(Wh[ks + tig][bn]);
                unsigned bh1 = __float_as_uint(Wh[ks + tig + 4][bn]);
                unsigned bl0 = __float_as_uint(Wlo[ks + tig][bn]);
                unsigned bl1 = __float_as_uint(Wlo[ks + tig + 4][bn]);
                mma_tf32(acc[j], ah[0], ah[1], ah[2], ah[3], bh0, bh1);
                mma_tf32(acc[j], ah[0], ah[1], ah[2], ah[3], bl0, bl1);
                mma_tf32(acc[j], al[0], al[1], al[2], al[3], bh0, bh1);
            }
        }
        __syncthreads();
    }

#pragma unroll
    for (int j = 0; j < 8; j++) {
        int c = chf * 64 + j * 8 + 2 * tig;   // combined col of acc[j][0]
        bool isP = (c < 64);
        float* buf = isP ? P : BASE;
        int cc = isP ? c : c - 64;
        float b0v = isP ? 0.0f : bl[cc];
        float b1v = isP ? 0.0f : bl[cc + 1];
        int r1 = row0 + rg * 16 + gid;
        if (r1 < N)
            *(float2*)(buf + r1 * 64 + cc) =
                make_float2(acc[j][0] + b0v, acc[j][1] + b1v);
        int r2 = r1 + 8;
        if (r2 < N)
            *(float2*)(buf + r2 * 64 + cc) =
                make_float2(acc[j][2] + b0v, acc[j][3] + b1v);
    }
}

// Gather v2: TWO nodes per warp, one per half-warp (16 lanes). Each lane
// loads a float4 -> 16 lanes cover the 256B neighbor row coalesced. Halves
// LDG instruction count and warp count vs v1; doubles in-flight bytes/warp.
// h[i] = elu(base[i] + inv[i] * sum_{j in N(i)} p[j]).
// PROJ: a[i] = h[i]@Wp_top + bp, b[i] = h[i]@Wp_bot via half-warp shuffle.
template <bool PROJ>
__global__ void gather_elu_kernel(const float* __restrict__ Wp,
                                  const float* __restrict__ bp) {
    __shared__ float Ws[512];
    if (PROJ) {
        for (int i = threadIdx.x; i < 512; i += blockDim.x) Ws[i] = Wp[i];
        __syncthreads();
    }
    int w = (blockIdx.x * blockDim.x + threadIdx.x) >> 4;   // node = global half-warp
    if (w >= N_NODES) return;
    int lane = threadIdx.x & 15;
    int beg = g_row[w], end = g_row[w + 1];

    const float4* P = (const float4*)g_p;
    float ax0 = 0.f, ay0 = 0.f, az0 = 0.f, aw0 = 0.f;
    float ax1 = 0.f, ay1 = 0.f, az1 = 0.f, aw1 = 0.f;
    int j = beg;
    for (; j + 1 < end; j += 2) {
        int s0 = g_csr[j], s1 = g_csr[j + 1];
        float4 v0 = P[s0 * 16 + lane];
        float4 v1 = P[s1 * 16 + lane];
        ax0 += v0.x; ay0 += v0.y; az0 += v0.z; aw0 += v0.w;
        ax1 += v1.x; ay1 += v1.y; az1 += v1.z; aw1 += v1.w;
    }
    if (j < end) {
        float4 v = P[g_csr[j] * 16 + lane];
        ax0 += v.x; ay0 += v.y; az0 += v.z; aw0 += v.w;
    }
    float inv = g_inv[w];
    float4 b = ((const float4*)g_base)[w * 16 + lane];
    float v0 = b.x + inv * (ax0 + ax1);
    float v1 = b.y + inv * (ay0 + ay1);
    float v2 = b.z + inv * (az0 + az1);
    float v3 = b.w + inv * (aw0 + aw1);
    v0 = v0 > 0.0f ? v0 : expm1f(v0);
    v1 = v1 > 0.0f ? v1 : expm1f(v1);
    v2 = v2 > 0.0f ? v2 : expm1f(v2);
    v3 = v3 > 0.0f ? v3 : expm1f(v3);
    ((float4*)g_h)[w * 16 + lane] = make_float4(v0, v1, v2, v3);

    if (PROJ) {
        // lane owns cols c0..c0+3 of the 64-wide h row
        int c0 = 4 * lane;
        float hv[4] = {v0, v1, v2, v3};
        float sa[4] = {0.f, 0.f, 0.f, 0.f}, sb[4] = {0.f, 0.f, 0.f, 0.f};
#pragma unroll
        for (int u = 0; u < 4; u++) {
#pragma unroll
            for (int o = 0; o < 4; o++) {
                sa[o] += hv[u] * Ws[(c0 + u) * 4 + o];
                sb[o] += hv[u] * Ws[(64 + c0 + u) * 4 + o];
            }
        }
        // reduce within the 16-lane half-warp (xor offsets stay in-group)
#pragma unroll
        for (int off = 8; off > 0; off >>= 1) {
#pragma unroll
            for (int o = 0; o < 4; o++) {
                sa[o] += __shfl_xor_sync(0xffffffffu, sa[o], off);
                sb[o] += __shfl_xor_sync(0xffffffffu, sb[o], off);
            }
        }
        if (lane == 0) {
            g_a[w] = make_float4(sa[0] + bp[0], sa[1] + bp[1],
                                 sa[2] + bp[2], sa[3] + bp[3]);
            g_b[w] = make_float4(sb[0], sb[1], sb[2], sb[3]);
        }
    }
}

// out[e] = a[src] + b[dst]
__global__ void edge_out_kernel(float* __restrict__ out, int E) {
    int e = blockIdx.x * blockDim.x + threadIdx.x;
    if (e >= E) return;
    float4 a = g_a[g_src[e]];
    float4 b = g_b[g_dst[e]];
    ((float4*)out)[e] = make_float4(a.x + b.x, a.y + b.y, a.z + b.z, a.w + b.w);
}

extern "C" void kernel_launch(void* const* d_in, const int* in_sizes, int n_in,
                              void* d_out, int out_size) {
    const float* x   = (const float*)d_in[0];
    const int*   eiw = (const int*)d_in[1];   // raw words; dtype probed on device
    const float* Wl1 = (const float*)d_in[2];
    const float* bl1 = (const float*)d_in[3];
    const float* Wr1 = (const float*)d_in[4];
    const float* Wl2 = (const float*)d_in[5];
    const float* bl2 = (const float*)d_in[6];
    const float* Wr2 = (const float*)d_in[7];
    const float* Wl3 = (const float*)d_in[8];
    const float* bl3 = (const float*)d_in[9];
    const float* Wr3 = (const float*)d_in[10];
    const float* Wp  = (const float*)d_in[11];
    const float* bp  = (const float*)d_in[12];
    float* out = (float*)d_out;

    int E = in_sizes[1] / 2;
    if (E > E_MAX) E = E_MAX;

    float* d_p;    cudaGetSymbolAddress((void**)&d_p,    g_p);
    float* d_base; cudaGetSymbolAddress((void**)&d_base, g_base);
    float* d_h;    cudaGetSymbolAddress((void**)&d_h,    g_h);

    // Side stream + events: overlap the CSR build (L2/atomic-bound) with the
    // layer-1 GEMM (tensor-bound). Created once, reused; fork/join via events
    // is graph-legal and deterministic.
    static cudaStream_t s_csr = nullptr;
    static cudaEvent_t ev_fork = nullptr, ev_join = nullptr;
    if (!s_csr) {
        cudaStreamCreateWithFlags(&s_csr, cudaStreamNonBlocking);
        cudaEventCreateWithFlags(&ev_fork, cudaEventDisableTiming);
        cudaEventCreateWithFlags(&ev_join, cudaEventDisableTiming);
    }

    const int TB = 256;
    int gN    = (N_NODES + TB - 1) / TB;
    int gE    = (E + TB - 1) / TB;
    int gGath = (N_NODES * 16 + TB - 1) / TB;      // 1 half-warp per node
    int gGemm = (N_NODES + 63) / 64;               // 64 rows per block

    // Fork: CSR build on side stream, layer-1 GEMM on main stream.
    cudaEventRecord(ev_fork, 0);
    cudaStreamWaitEvent(s_csr, ev_fork, 0);

    zero_cnt_kernel<<<gN, TB, 0, s_csr>>>();
    convert_count_kernel<<<gE, TB, 0, s_csr>>>(eiw, E);
    scan_kernel<<<1, 1024, 0, s_csr>>>();
    fill_kernel<<<gE, TB, 0, s_csr>>>(E);
    cudaEventRecord(ev_join, s_csr);

    // Layer 1 (K=128) runs concurrently with the CSR build
    gemm2_kernel<<<gGemm, 256>>>(x, Wl1, Wr1, bl1, d_p, d_base, N_NODES, 128);

    // Join: gather needs CSR + GEMM1 results
    cudaStreamWaitEvent(0, ev_join, 0);
    gather_elu_kernel<false><<<gGath, TB>>>(nullptr, nullptr);

    // Layer 2 (K=64)
    gemm2_kernel<<<gGemm, 256>>>(d_h, Wl2, Wr2, bl2, d_p, d_base, N_NODES, 64);
    gather_elu_kernel<false><<<gGath, TB>>>(nullptr, nullptr);

    // Layer 3 (K=64) + fused edge-MLP projection
    gemm2_kernel<<<gGemm, 256>>>(d_h, Wl3, Wr3, bl3, d_p, d_base, N_NODES, 64);
    gather_elu_kernel<true><<<gGath, TB>>>(Wp, bp);

    // out[e] = a[src] + b[dst]
    edge_out_kernel<<<gE, TB>>>(out, E);
}

// round 15
// speedup vs baseline: 1.0313x; 1.0313x over previous
#include <cuda_runtime.h>
#include <math.h>

#define N_NODES 50000
#define E_MAX   800000
#define D_H 64
#define KC 16   // K-chunk for tf32 GEMM

// Scratch (device globals -- no allocation allowed)
__device__ float g_p[N_NODES * D_H];      // x @ Wl
__device__ float g_base[N_NODES * D_H];   // x @ Wr + bl
__device__ float g_h[N_NODES * D_H];      // elu(...) -> next layer input
__device__ int   g_cnt[N_NODES];
__device__ float g_inv[N_NODES];
__device__ int   g_row[N_NODES + 1];      // CSR row offsets (by dst)
__device__ int   g_cursor[N_NODES];
__device__ int   g_csr[E_MAX];            // src indices grouped by dst
__device__ int   g_src[E_MAX];
__device__ int   g_dst[E_MAX];
__device__ float4 g_a[N_NODES];           // h @ Wp_top + bp
__device__ float4 g_b[N_NODES];           // h @ Wp_bot

__device__ __forceinline__ unsigned f2tf32(float x) {
    unsigned r;
    asm("cvt.rna.tf32.f32 %0, %1;" : "=r"(r) : "f"(x));
    return r;
}

__device__ __forceinline__ void mma_tf32(float c[4],
        unsigned a0, unsigned a1, unsigned a2, unsigned a3,
        unsigned b0, unsigned b1) {
    asm volatile(
        "mma.sync.aligned.m16n8k8.row.col.f32.tf32.tf32.f32 "
        "{%0,%1,%2,%3}, {%4,%5,%6,%7}, {%8,%9}, {%0,%1,%2,%3};"
        : "+f"(c[0]), "+f"(c[1]), "+f"(c[2]), "+f"(c[3])
        : "r"(a0), "r"(a1), "r"(a2), "r"(a3), "r"(b0), "r"(b1));
}

__global__ void zero_cnt_kernel() {
    int i = blockIdx.x * blockDim.x + threadIdx.x;
    if (i < N_NODES) g_cnt[i] = 0;
}

// decode src/dst (+ count degrees) in one pass. int64-vs-int32 detection is
// done per block from the first 128 words (all L2-broadcast): for int64
// indices < 2^31 every odd word is 0; for 64 random int32 indices it isn't.
__global__ void convert_count_kernel(const int* __restrict__ w, int E) {
    __shared__ int is64_s;
    if (threadIdx.x == 0) {
        int z = 1;
        for (int i = 1; i < 129; i += 2)
            if (w[i] != 0) { z = 0; break; }
        is64_s = z;
    }
    __syncthreads();
    int is64 = is64_s;
    int e = blockIdx.x * blockDim.x + threadIdx.x;
    if (e >= E) return;
    int s, d;
    if (is64) { s = w[2 * e]; d = w[2 * (E + e)]; }
    else      { s = w[e];     d = w[E + e]; }
    g_src[e] = s;
    g_dst[e] = d;
    atomicAdd(&g_cnt[d], 1);
}

// Single block, 1024 threads: exclusive scan of g_cnt -> g_row, g_cursor, g_inv
__global__ void scan_kernel() {
    __shared__ int sums[1024];
    int t = threadIdx.x;
    const int CH = (N_NODES + 1023) / 1024;
    int begin = t * CH;
    int end = begin + CH; if (end > N_NODES) end = N_NODES;
    int s = 0;
    for (int i = begin; i < end; i++) s += g_cnt[i];
    sums[t] = s;
    __syncthreads();
    for (int off = 1; off < 1024; off <<= 1) {
        int v = (t >= off) ? sums[t - off] : 0;
        __syncthreads();
        sums[t] += v;
        __syncthreads();
    }
    int run = (t == 0) ? 0 : sums[t - 1];
    for (int i = begin; i < end; i++) {
        g_row[i] = run;
        g_cursor[i] = run;
        int c = g_cnt[i];
        run += c;
        g_inv[i] = 1.0f / (float)(c > 1 ? c : 1);
    }
    if (t == 1023) g_row[N_NODES] = run;
}

__global__ void fill_kernel(int E) {
    int e = blockIdx.x * blockDim.x + threadIdx.x;
    if (e < E) {
        int pos = atomicAdd(&g_cursor[g_dst[e]], 1);
        g_csr[pos] = g_src[e];
    }
}

// Fused dual GEMM on tensor cores (tf32, 3-term split precision):
//   P = X @ Wl ; BASE = X @ Wr + bl.   (R11 version, proven)
__global__ void __launch_bounds__(256) gemm2_kernel(
        const float* __restrict__ X,
        const float* __restrict__ Wl, const float* __restrict__ Wr,
        const float* __restrict__ bl,
        float* __restrict__ P, float* __restrict__ BASE,
        int N, int K) {
    __shared__ float Xh[KC][72], Xlo[KC][72];     // [k][row], rows 0..63
    __shared__ float Wh[KC][136], Wlo[KC][136];   // [k][combined col 0..127]
    int tid  = threadIdx.x;
    int warp = tid >> 5, lane = tid & 31;
    int gid  = lane >> 2, tig = lane & 3;
    int rg   = warp >> 1;            // row group: rows rg*16..rg*16+15
    int chf  = warp & 1;             // col half:  cols chf*64..chf*64+63
    int row0 = blockIdx.x * 64;

    float acc[8][4];
#pragma unroll
    for (int j = 0; j < 8; j++)
#pragma unroll
        for (int q = 0; q < 4; q++) acc[j][q] = 0.0f;

    for (int k0 = 0; k0 < K; k0 += KC) {
        {
            int r  = tid >> 2;           // 0..63
            int kq = (tid & 3) * 4;      // 0,4,8,12
            int grow = row0 + r;
            float4 v = make_float4(0.f, 0.f, 0.f, 0.f);
            if (grow < N) v = *(const float4*)(X + (long)grow * K + k0 + kq);
            float xv[4] = {v.x, v.y, v.z, v.w};
#pragma unroll
            for (int u = 0; u < 4; u++) {
                unsigned h = f2tf32(xv[u]);
                float hf = __uint_as_float(h);
                Xh[kq + u][r]  = hf;
                Xlo[kq + u][r] = __uint_as_float(f2tf32(xv[u] - hf));
            }
        }
#pragma unroll
        for (int i = 0; i < 2; i++) {
            int f  = tid + i * 256;      // 0..511 float4 slots
            int k  = f >> 5;             // 0..15
            int c0 = (f & 31) * 4;       // 0..124
            const float* src = (c0 < 64) ? (Wl + (k0 + k) * 64 + c0)
                                         : (Wr + (k0 + k) * 64 + c0 - 64);
            float4 v = *(const float4*)src;
            float wv[4] = {v.x, v.y, v.z, v.w};
#pragma unroll
            for (int u = 0; u < 4; u++) {
                unsigned h = f2tf32(wv[u]);
                float hf = __uint_as_float(h);
                Wh[k][c0 + u]  = hf;
                Wlo[k][c0 + u] = __uint_as_float(f2tf32(wv[u] - hf));
            }
        }
        __syncthreads();

#pragma unroll
        for (int ks = 0; ks < KC; ks += 8) {
            int arow = rg * 16 + gid;
            unsigned ah[4], al[4];
            ah[0] = __float_as_uint(Xh[ks + tig][arow]);
            ah[1] = __float_as_uint(Xh[ks + tig][arow + 8]);
            ah[2] = __float_as_uint(Xh[ks + tig + 4][arow]);
            ah[3] = __float_as_uint(Xh[ks + tig + 4][arow + 8]);
            al[0] = __float_as_uint(Xlo[ks + tig][arow]);
            al[1] = __float_as_uint(Xlo[ks + tig][arow + 8]);
            al[2] = __float_as_uint(Xlo[ks + tig + 4][arow]);
            al[3] = __float_as_uint(Xlo[ks + tig + 4][arow + 8]);
#pragma unroll
            for (int j = 0; j < 8; j++) {
                int bn = chf * 64 + j * 8 + gid;
                unsigned bh0 = __float_as_uint(Wh[ks + tig][bn]);
                unsigned bh1 = __float_as_uint(Wh[ks + tig + 4][bn]);
                unsigned bl0 = __float_as_uint(Wlo[ks + tig][bn]);
                unsigned bl1 = __float_as_uint(Wlo[ks + tig + 4][bn]);
                mma_tf32(acc[j], ah[0], ah[1], ah[2], ah[3], bh0, bh1);
                mma_tf32(acc[j], ah[0], ah[1], ah[2], ah[3], bl0, bl1);
                mma_tf32(acc[j], al[0], al[1], al[2], al[3], bh0, bh1);
            }
        }
        __syncthreads();
    }

#pragma unroll
    for (int j = 0; j < 8; j++) {
        int c = chf * 64 + j * 8 + 2 * tig;   // combined col of acc[j][0]
        bool isP = (c < 64);
        float* buf = isP ? P : BASE;
        int cc = isP ? c : c - 64;
        float b0v = isP ? 0.0f : bl[cc];
        float b1v = isP ? 0.0f : bl[cc + 1];
        int r1 = row0 + rg * 16 + gid;
        if (r1 < N)
            *(float2*)(buf + r1 * 64 + cc) =
                make_float2(acc[j][0] + b0v, acc[j][1] + b1v);
        int r2 = r1 + 8;
        if (r2 < N)
            *(float2*)(buf + r2 * 64 + cc) =
                make_float2(acc[j][2] + b0v, acc[j][3] + b1v);
    }
}

// h[i] = elu(base[i] + inv[i] * sum_{j in N(i)} p[j]) — one warp per node,
// lane handles 2 floats (float2), unroll x2 (proven v1 form).
// PROJ: additionally a[i] = h[i]@Wp_top + bp, b[i] = h[i]@Wp_bot via warp
// shuffle reduction (Wp staged in shared).
template <bool PROJ>
__global__ void gather_elu_kernel(const float* __restrict__ Wp,
                                  const float* __restrict__ bp) {
    __shared__ float Ws[512];
    if (PROJ) {
        for (int i = threadIdx.x; i < 512; i += blockDim.x) Ws[i] = Wp[i];
        __syncthreads();
    }
    int w = (blockIdx.x * blockDim.x + threadIdx.x) >> 5;
    if (w >= N_NODES) return;
    int lane = threadIdx.x & 31;
    int beg = g_row[w], end = g_row[w + 1];

    const float2* P = (const float2*)g_p;
    float ax = 0.0f, ay = 0.0f;
    int j = beg;
    for (; j + 1 < end; j += 2) {
        int s0 = g_csr[j], s1 = g_csr[j + 1];
        float2 v0 = P[s0 * 32 + lane];
        float2 v1 = P[s1 * 32 + lane];
        ax += v0.x + v1.x;
        ay += v0.y + v1.y;
    }
    if (j < end) {
        float2 v = P[g_csr[j] * 32 + lane];
        ax += v.x; ay += v.y;
    }
    float inv = g_inv[w];
    float2 b = ((const float2*)g_base)[w * 32 + lane];
    float vx = b.x + inv * ax;
    float vy = b.y + inv * ay;
    vx = vx > 0.0f ? vx : expm1f(vx);
    vy = vy > 0.0f ? vy : expm1f(vy);
    ((float2*)g_h)[w * 32 + lane] = make_float2(vx, vy);

    if (PROJ) {
        int c0 = 2 * lane;
        float sa[4], sb[4];
#pragma unroll
        for (int o = 0; o < 4; o++) {
            sa[o] = vx * Ws[c0 * 4 + o]        + vy * Ws[(c0 + 1) * 4 + o];
            sb[o] = vx * Ws[(64 + c0) * 4 + o] + vy * Ws[(64 + c0 + 1) * 4 + o];
        }
#pragma unroll
        for (int off = 16; off > 0; off >>= 1) {
#pragma unroll
            for (int o = 0; o < 4; o++) {
                sa[o] += __shfl_xor_sync(0xffffffffu, sa[o], off);
                sb[o] += __shfl_xor_sync(0xffffffffu, sb[o], off);
            }
        }
        if (lane == 0) {
            g_a[w] = make_float4(sa[0] + bp[0], sa[1] + bp[1],
                                 sa[2] + bp[2], sa[3] + bp[3]);
            g_b[w] = make_float4(sb[0], sb[1], sb[2], sb[3]);
        }
    }
}

// out[e] = a[src] + b[dst]
__global__ void edge_out_kernel(float* __restrict__ out, int E) {
    int e = blockIdx.x * blockDim.x + threadIdx.x;
    if (e >= E) return;
    float4 a = g_a[g_src[e]];
    float4 b = g_b[g_dst[e]];
    ((float4*)out)[e] = make_float4(a.x + b.x, a.y + b.y, a.z + b.z, a.w + b.w);
}

extern "C" void kernel_launch(void* const* d_in, const int* in_sizes, int n_in,
                              void* d_out, int out_size) {
    const float* x   = (const float*)d_in[0];
    const int*   eiw = (const int*)d_in[1];   // raw words; dtype probed on device
    const float* Wl1 = (const float*)d_in[2];
    const float* bl1 = (const float*)d_in[3];
    const float* Wr1 = (const float*)d_in[4];
    const float* Wl2 = (const float*)d_in[5];
    const float* bl2 = (const float*)d_in[6];
    const float* Wr2 = (const float*)d_in[7];
    const float* Wl3 = (const float*)d_in[8];
    const float* bl3 = (const float*)d_in[9];
    const float* Wr3 = (const float*)d_in[10];
    const float* Wp  = (const float*)d_in[11];
    const float* bp  = (const float*)d_in[12];
    float* out = (float*)d_out;

    int E = in_sizes[1] / 2;
    if (E > E_MAX) E = E_MAX;

    float* d_p;    cudaGetSymbolAddress((void**)&d_p,    g_p);
    float* d_base; cudaGetSymbolAddress((void**)&d_base, g_base);
    float* d_h;    cudaGetSymbolAddress((void**)&d_h,    g_h);

    // Side stream + events: overlap the CSR build (L2/atomic-bound) with the
    // layer-1 GEMM (tensor-bound). Created once, reused; fork/join via events
    // is graph-legal and deterministic.
    static cudaStream_t s_csr = nullptr;
    static cudaEvent_t ev_fork = nullptr, ev_join = nullptr;
    if (!s_csr) {
        cudaStreamCreateWithFlags(&s_csr, cudaStreamNonBlocking);
        cudaEventCreateWithFlags(&ev_fork, cudaEventDisableTiming);
        cudaEventCreateWithFlags(&ev_join, cudaEventDisableTiming);
    }

    const int TB = 256;
    int gN    = (N_NODES + TB - 1) / TB;
    int gE    = (E + TB - 1) / TB;
    int gGath = (N_NODES * 32 + TB - 1) / TB;      // 1 warp per node
    int gGemm = (N_NODES + 63) / 64;               // 64 rows per block

    // Fork: CSR build on side stream, layer-1 GEMM on main stream.
    // SUBMISSION ORDER puts gemm2_kernel at slot #4 (ncu -s 5 profiles the
    // 4th submitted kernel) while execution order is unchanged: the side
    // stream runs zero->convert->scan->fill in order; gemm1 runs on main.
    cudaEventRecord(ev_fork, 0);
    cudaStreamWaitEvent(s_csr, ev_fork, 0);

    zero_cnt_kernel<<<gN, TB, 0, s_csr>>>();                 // sub #1
    convert_count_kernel<<<gE, TB, 0, s_csr>>>(eiw, E);      // sub #2
    scan_kernel<<<1, 1024, 0, s_csr>>>();                    // sub #3

    // Layer 1 (K=128) runs concurrently with the CSR build  -- sub #4
    gemm2_kernel<<<gGemm, 256>>>(x, Wl1, Wr1, bl1, d_p, d_base, N_NODES, 128);

    fill_kernel<<<gE, TB, 0, s_csr>>>(E);                    // sub #5
    cudaEventRecord(ev_join, s_csr);

    // Join: gather needs CSR + GEMM1 results
    cudaStreamWaitEvent(0, ev_join, 0);
    gather_elu_kernel<false><<<gGath, TB>>>(nullptr, nullptr);

    // Layer 2 (K=64)
    gemm2_kernel<<<gGemm, 256>>>(d_h, Wl2, Wr2, bl2, d_p, d_base, N_NODES, 64);
    gather_elu_kernel<false><<<gGath, TB>>>(nullptr, nullptr);

    // Layer 3 (K=64) + fused edge-MLP projection
    gemm2_kernel<<<gGemm, 256>>>(d_h, Wl3, Wr3, bl3, d_p, d_base, N_NODES, 64);
    gather_elu_kernel<true><<<gGath, TB>>>(Wp, bp);

    // out[e] = a[src] + b[dst]
    edge_out_kernel<<<gE, TB>>>(out, E);
}

// round 16
// speedup vs baseline: 1.0441x; 1.0124x over previous
#include <cuda_runtime.h>
#include <math.h>

#define N_NODES 50000
#define E_MAX   800000
#define D_H 64
#define KC 16   // K-chunk for tf32 GEMM

// Scratch (device globals -- no allocation allowed)
__device__ float g_p[N_NODES * D_H];      // x @ Wl
__device__ float g_base[N_NODES * D_H];   // x @ Wr + bl
__device__ float g_h[N_NODES * D_H];      // elu(...) -> next layer input
__device__ int   g_cnt[N_NODES];
__device__ float g_inv[N_NODES];
__device__ int   g_row[N_NODES + 1];      // CSR row offsets (by dst)
__device__ int   g_cursor[N_NODES];
__device__ int   g_csr[E_MAX];            // src indices grouped by dst
__device__ int   g_src[E_MAX];
__device__ int   g_dst[E_MAX];
__device__ float4 g_a[N_NODES];           // h @ Wp_top + bp
__device__ float4 g_b[N_NODES];           // h @ Wp_bot

__device__ __forceinline__ unsigned f2tf32(float x) {
    unsigned r;
    asm("cvt.rna.tf32.f32 %0, %1;" : "=r"(r) : "f"(x));
    return r;
}

__device__ __forceinline__ void mma_tf32(float c[4],
        const unsigned a[4], unsigned b0, unsigned b1) {
    asm volatile(
        "mma.sync.aligned.m16n8k8.row.col.f32.tf32.tf32.f32 "
        "{%0,%1,%2,%3}, {%4,%5,%6,%7}, {%8,%9}, {%0,%1,%2,%3};"
        : "+f"(c[0]), "+f"(c[1]), "+f"(c[2]), "+f"(c[3])
        : "r"(a[0]), "r"(a[1]), "r"(a[2]), "r"(a[3]), "r"(b0), "r"(b1));
}

__global__ void zero_cnt_kernel() {
    int i = blockIdx.x * blockDim.x + threadIdx.x;
    if (i < N_NODES) g_cnt[i] = 0;
}

// decode src/dst (+ count degrees) in one pass. int64-vs-int32 detection is
// done per block from the first 128 words (all L2-broadcast): for int64
// indices < 2^31 every odd word is 0; for 64 random int32 indices it isn't.
__global__ void convert_count_kernel(const int* __restrict__ w, int E) {
    __shared__ int is64_s;
    if (threadIdx.x == 0) {
        int z = 1;
        for (int i = 1; i < 129; i += 2)
            if (w[i] != 0) { z = 0; break; }
        is64_s = z;
    }
    __syncthreads();
    int is64 = is64_s;
    int e = blockIdx.x * blockDim.x + threadIdx.x;
    if (e >= E) return;
    int s, d;
    if (is64) { s = w[2 * e]; d = w[2 * (E + e)]; }
    else      { s = w[e];     d = w[E + e]; }
    g_src[e] = s;
    g_dst[e] = d;
    atomicAdd(&g_cnt[d], 1);
}

// Single block, 1024 threads: exclusive scan of g_cnt -> g_row, g_cursor, g_inv
__global__ void scan_kernel() {
    __shared__ int sums[1024];
    int t = threadIdx.x;
    const int CH = (N_NODES + 1023) / 1024;
    int begin = t * CH;
    int end = begin + CH; if (end > N_NODES) end = N_NODES;
    int s = 0;
    for (int i = begin; i < end; i++) s += g_cnt[i];
    sums[t] = s;
    __syncthreads();
    for (int off = 1; off < 1024; off <<= 1) {
        int v = (t >= off) ? sums[t - off] : 0;
        __syncthreads();
        sums[t] += v;
        __syncthreads();
    }
    int run = (t == 0) ? 0 : sums[t - 1];
    for (int i = begin; i < end; i++) {
        g_row[i] = run;
        g_cursor[i] = run;
        int c = g_cnt[i];
        run += c;
        g_inv[i] = 1.0f / (float)(c > 1 ? c : 1);
    }
    if (t == 1023) g_row[N_NODES] = run;
}

__global__ void fill_kernel(int E) {
    int e = blockIdx.x * blockDim.x + threadIdx.x;
    if (e < E) {
        int pos = atomicAdd(&g_cursor[g_dst[e]], 1);
        g_csr[pos] = g_src[e];
    }
}

// Fused dual GEMM on tensor cores (tf32, 3-term split precision):
//   P = X @ Wl ; BASE = X @ Wr + bl.
// SWAPPED-ROLE mainloop (v2): W is the MMA A-operand (M = combined cols),
// X is the B-operand (N = rows). Each warp owns a 32-row x 32-col tile
// (2 col-tiles x 4 row-tiles): per 8-k step 32 scalar LDS feed 24 MMAs
// (vs 48 in v1) -- cuts shared-pipe pressure ~33% at same MMA count.
// Staging layouts are unchanged from v1.
__global__ void __launch_bounds__(256) gemm2_kernel(
        const float* __restrict__ X,
        const float* __restrict__ Wl, const float* __restrict__ Wr,
        const float* __restrict__ bl,
        float* __restrict__ P, float* __restrict__ BASE,
        int N, int K) {
    __shared__ float Xh[KC][72], Xlo[KC][72];     // [k][row], rows 0..63
    __shared__ float Wh[KC][136], Wlo[KC][136];   // [k][combined col 0..127]
    int tid  = threadIdx.x;
    int warp = tid >> 5, lane = tid & 31;
    int gid  = lane >> 2, tig = lane & 3;
    int rowbase = (warp & 1) * 32;   // warp's 32 rows
    int colbase = (warp >> 1) * 32;  // warp's 32 combined cols
    int row0 = blockIdx.x * 64;

    float acc[2][4][4];              // [col-tile][row-tile][frag]
#pragma unroll
    for (int ct = 0; ct < 2; ct++)
#pragma unroll
        for (int rt = 0; rt < 4; rt++)
#pragma unroll
            for (int q = 0; q < 4; q++) acc[ct][rt][q] = 0.0f;

    for (int k0 = 0; k0 < K; k0 += KC) {
        // stage X tile: 64 rows x KC k, transposed + hi/lo split (as v1)
        {
            int r  = tid >> 2;           // 0..63
            int kq = (tid & 3) * 4;      // 0,4,8,12
            int grow = row0 + r;
            float4 v = make_float4(0.f, 0.f, 0.f, 0.f);
            if (grow < N) v = *(const float4*)(X + (long)grow * K + k0 + kq);
            float xv[4] = {v.x, v.y, v.z, v.w};
#pragma unroll
            for (int u = 0; u < 4; u++) {
                unsigned h = f2tf32(xv[u]);
                float hf = __uint_as_float(h);
                Xh[kq + u][r]  = hf;
                Xlo[kq + u][r] = __uint_as_float(f2tf32(xv[u] - hf));
            }
        }
        // stage combined W tile: KC k x 128 cols, hi/lo split (as v1)
#pragma unroll
        for (int i = 0; i < 2; i++) {
            int f  = tid + i * 256;      // 0..511 float4 slots
            int k  = f >> 5;             // 0..15
            int c0 = (f & 31) * 4;       // 0..124
            const float* src = (c0 < 64) ? (Wl + (k0 + k) * 64 + c0)
                                         : (Wr + (k0 + k) * 64 + c0 - 64);
            float4 v = *(const float4*)src;
            float wv[4] = {v.x, v.y, v.z, v.w};
#pragma unroll
            for (int u = 0; u < 4; u++) {
                unsigned h = f2tf32(wv[u]);
                float hf = __uint_as_float(h);
                Wh[k][c0 + u]  = hf;
                Wlo[k][c0 + u] = __uint_as_float(f2tf32(wv[u] - hf));
            }
        }
        __syncthreads();

#pragma unroll
        for (int ks = 0; ks < KC; ks += 8) {
            // B-fragments (X): 4 row-tiles x {hi,lo} x 2 regs
            unsigned bh[4][2], blo[4][2];
#pragma unroll
            for (int rt = 0; rt < 4; rt++) {
                int r = rowbase + rt * 8 + gid;
                bh[rt][0]  = __float_as_uint(Xh[ks + tig][r]);
                bh[rt][1]  = __float_as_uint(Xh[ks + tig + 4][r]);
                blo[rt][0] = __float_as_uint(Xlo[ks + tig][r]);
                blo[rt][1] = __float_as_uint(Xlo[ks + tig + 4][r]);
            }
#pragma unroll
            for (int ct = 0; ct < 2; ct++) {
                int c = colbase + ct * 16 + gid;
                unsigned ah[4], al[4];
                ah[0] = __float_as_uint(Wh[ks + tig][c]);
                ah[1] = __float_as_uint(Wh[ks + tig][c + 8]);
                ah[2] = __float_as_uint(Wh[ks + tig + 4][c]);
                ah[3] = __float_as_uint(Wh[ks + tig + 4][c + 8]);
                al[0] = __float_as_uint(Wlo[ks + tig][c]);
                al[1] = __float_as_uint(Wlo[ks + tig][c + 8]);
                al[2] = __float_as_uint(Wlo[ks + tig + 4][c]);
                al[3] = __float_as_uint(Wlo[ks + tig + 4][c + 8]);
#pragma unroll
                for (int rt = 0; rt < 4; rt++) {
                    mma_tf32(acc[ct][rt], ah, bh[rt][0], bh[rt][1]);   // Wh*Xh
                    mma_tf32(acc[ct][rt], ah, blo[rt][0], blo[rt][1]); // Wh*Xl
                    mma_tf32(acc[ct][rt], al, bh[rt][0], bh[rt][1]);   // Wl*Xh
                }
            }
        }
        __syncthreads();
    }

    // epilogue: acc[ct][rt] = {(col,row), (col,row+1), (col+8,row), (col+8,row+1)}
    // with col = colbase+ct*16+gid, row = row0+rowbase+rt*8+2*tig.
#pragma unroll
    for (int ct = 0; ct < 2; ct++) {
        int c = colbase + ct * 16 + gid;     // combined col (block of 16 never straddles 64)
        bool isP = (c < 64);
        float* buf = isP ? P : BASE;
        int cc = isP ? c : c - 64;
        float b0v = isP ? 0.0f : bl[cc];
        float b8v = isP ? 0.0f : bl[cc + 8];
#pragma unroll
        for (int rt = 0; rt < 4; rt++) {
            int row = row0 + rowbase + rt * 8 + 2 * tig;
            if (row < N) {
                buf[row * 64 + cc]     = acc[ct][rt][0] + b0v;
                buf[row * 64 + cc + 8] = acc[ct][rt][2] + b8v;
            }
            if (row + 1 < N) {
                buf[(row + 1) * 64 + cc]     = acc[ct][rt][1] + b0v;
                buf[(row + 1) * 64 + cc + 8] = acc[ct][rt][3] + b8v;
            }
        }
    }
}

// h[i] = elu(base[i] + inv[i] * sum_{j in N(i)} p[j]) — one warp per node,
// lane handles 2 floats (float2), unroll x2 (proven v1 form).
// PROJ: additionally a[i] = h[i]@Wp_top + bp, b[i] = h[i]@Wp_bot via warp
// shuffle reduction (Wp staged in shared).
template <bool PROJ>
__global__ void gather_elu_kernel(const float* __restrict__ Wp,
                                  const float* __restrict__ bp) {
    __shared__ float Ws[512];
    if (PROJ) {
        for (int i = threadIdx.x; i < 512; i += blockDim.x) Ws[i] = Wp[i];
        __syncthreads();
    }
    int w = (blockIdx.x * blockDim.x + threadIdx.x) >> 5;
    if (w >= N_NODES) return;
    int lane = threadIdx.x & 31;
    int beg = g_row[w], end = g_row[w + 1];

    const float2* P = (const float2*)g_p;
    float ax = 0.0f, ay = 0.0f;
    int j = beg;
    for (; j + 1 < end; j += 2) {
        int s0 = g_csr[j], s1 = g_csr[j + 1];
        float2 v0 = P[s0 * 32 + lane];
        float2 v1 = P[s1 * 32 + lane];
        ax += v0.x + v1.x;
        ay += v0.y + v1.y;
    }
    if (j < end) {
        float2 v = P[g_csr[j] * 32 + lane];
        ax += v.x; ay += v.y;
    }
    float inv = g_inv[w];
    float2 b = ((const float2*)g_base)[w * 32 + lane];
    float vx = b.x + inv * ax;
    float vy = b.y + inv * ay;
    vx = vx > 0.0f ? vx : expm1f(vx);
    vy = vy > 0.0f ? vy : expm1f(vy);
    ((float2*)g_h)[w * 32 + lane] = make_float2(vx, vy);

    if (PROJ) {
        int c0 = 2 * lane;
        float sa[4], sb[4];
#pragma unroll
        for (int o = 0; o < 4; o++) {
            sa[o] = vx * Ws[c0 * 4 + o]        + vy * Ws[(c0 + 1) * 4 + o];
            sb[o] = vx * Ws[(64 + c0) * 4 + o] + vy * Ws[(64 + c0 + 1) * 4 + o];
        }
#pragma unroll
        for (int off = 16; off > 0; off >>= 1) {
#pragma unroll
            for (int o = 0; o < 4; o++) {
                sa[o] += __shfl_xor_sync(0xffffffffu, sa[o], off);
                sb[o] += __shfl_xor_sync(0xffffffffu, sb[o], off);
            }
        }
        if (lane == 0) {
            g_a[w] = make_float4(sa[0] + bp[0], sa[1] + bp[1],
                                 sa[2] + bp[2], sa[3] + bp[3]);
            g_b[w] = make_float4(sb[0], sb[1], sb[2], sb[3]);
        }
    }
}

// out[e] = a[src] + b[dst]
__global__ void edge_out_kernel(float* __restrict__ out, int E) {
    int e = blockIdx.x * blockDim.x + threadIdx.x;
    if (e >= E) return;
    float4 a = g_a[g_src[e]];
    float4 b = g_b[g_dst[e]];
    ((float4*)out)[e] = make_float4(a.x + b.x, a.y + b.y, a.z + b.z, a.w + b.w);
}

extern "C" void kernel_launch(void* const* d_in, const int* in_sizes, int n_in,
                              void* d_out, int out_size) {
    const float* x   = (const float*)d_in[0];
    const int*   eiw = (const int*)d_in[1];   // raw words; dtype probed on device
    const float* Wl1 = (const float*)d_in[2];
    const float* bl1 = (const float*)d_in[3];
    const float* Wr1 = (const float*)d_in[4];
    const float* Wl2 = (const float*)d_in[5];
    const float* bl2 = (const float*)d_in[6];
    const float* Wr2 = (const float*)d_in[7];
    const float* Wl3 = (const float*)d_in[8];
    const float* bl3 = (const float*)d_in[9];
    const float* Wr3 = (const float*)d_in[10];
    const float* Wp  = (const float*)d_in[11];
    const float* bp  = (const float*)d_in[12];
    float* out = (float*)d_out;

    int E = in_sizes[1] / 2;
    if (E > E_MAX) E = E_MAX;

    float* d_p;    cudaGetSymbolAddress((void**)&d_p,    g_p);
    float* d_base; cudaGetSymbolAddress((void**)&d_base, g_base);
    float* d_h;    cudaGetSymbolAddress((void**)&d_h,    g_h);

    // Side stream + events: overlap the CSR build (L2/atomic-bound) with the
    // layer-1 GEMM (tensor-bound). Created once, reused; fork/join via events
    // is graph-legal and deterministic.
    static cudaStream_t s_csr = nullptr;
    static cudaEvent_t ev_fork = nullptr, ev_join = nullptr;
    if (!s_csr) {
        cudaStreamCreateWithFlags(&s_csr, cudaStreamNonBlocking);
        cudaEventCreateWithFlags(&ev_fork, cudaEventDisableTiming);
        cudaEventCreateWithFlags(&ev_join, cudaEventDisableTiming);
    }

    const int TB = 256;
    int gN    = (N_NODES + TB - 1) / TB;
    int gE    = (E + TB - 1) / TB;
    int gGath = (N_NODES * 32 + TB - 1) / TB;      // 1 warp per node
    int gGemm = (N_NODES + 63) / 64;               // 64 rows per block

    // Fork: CSR build on side stream, layer-1 GEMM on main stream.
    // Submission order keeps gemm2_kernel at slot #4 for ncu (-s 5).
    cudaEventRecord(ev_fork, 0);
    cudaStreamWaitEvent(s_csr, ev_fork, 0);

    zero_cnt_kernel<<<gN, TB, 0, s_csr>>>();                 // sub #1
    convert_count_kernel<<<gE, TB, 0, s_csr>>>(eiw, E);      // sub #2
    scan_kernel<<<1, 1024, 0, s_csr>>>();                    // sub #3

    // Layer 1 (K=128) runs concurrently with the CSR build  -- sub #4
    gemm2_kernel<<<gGemm, 256>>>(x, Wl1, Wr1, bl1, d_p, d_base, N_NODES, 128);

    fill_kernel<<<gE, TB, 0, s_csr>>>(E);                    // sub #5
    cudaEventRecord(ev_join, s_csr);

    // Join: gather needs CSR + GEMM1 results
    cudaStreamWaitEvent(0, ev_join, 0);
    gather_elu_kernel<false><<<gGath, TB>>>(nullptr, nullptr);

    // Layer 2 (K=64)
    gemm2_kernel<<<gGemm, 256>>>(d_h, Wl2, Wr2, bl2, d_p, d_base, N_NODES, 64);
    gather_elu_kernel<false><<<gGath, TB>>>(nullptr, nullptr);

    // Layer 3 (K=64) + fused edge-MLP projection
    gemm2_kernel<<<gGemm, 256>>>(d_h, Wl3, Wr3, bl3, d_p, d_base, N_NODES, 64);
    gather_elu_kernel<true><<<gGath, TB>>>(Wp, bp);

    // out[e] = a[src] + b[dst]
    edge_out_kernel<<<gE, TB>>>(out, E);
}